// round 10
// baseline (speedup 1.0000x reference)
#include <cuda_runtime.h>
#include <cuda_fp16.h>
#include <cstdint>

#define HN 128
#define FF 256
#define NMAX 50048
#define EMAX 800000
#define EPS 1e-5f

// ---------------- static scratch ----------------
__device__ float  g_P[(size_t)NMAX * FF];
__device__ __half g_h16[(size_t)EMAX * FF];
__device__ float  g_agg[(size_t)NMAX * HN];
__device__ uint2  g_Wt16[2][2][4096];            // [mode][half] B fp16 frag-packed
__device__ float  g_stats1[2 * FF];
__device__ float  g_stats2[2 * HN];
__device__ float  g_scale[FF];
__device__ float  g_shift[FF];
__device__ int    g_is64;

// ---------------- helpers ----------------
__device__ __forceinline__ float sigmoidf_(float x) {
    return __fdividef(1.f, 1.f + __expf(-x));
}
__device__ __forceinline__ float tanhf_(float x) {
    float t = __expf(2.f * x);
    return 1.f - __fdividef(2.f, t + 1.f);
}
__device__ __forceinline__ void mma16(float* c, const uint4 a, const uint2 b) {
    asm volatile("mma.sync.aligned.m16n8k16.row.col.f32.f16.f16.f32 "
                 "{%0,%1,%2,%3},{%4,%5,%6,%7},{%8,%9},{%0,%1,%2,%3};"
                 : "+f"(c[0]), "+f"(c[1]), "+f"(c[2]), "+f"(c[3])
                 : "r"(a.x), "r"(a.y), "r"(a.z), "r"(a.w), "r"(b.x), "r"(b.y));
}
__device__ __forceinline__ uint32_t h2u(__half2 h) {
    return *reinterpret_cast<uint32_t*>(&h);
}

// ---------------- small kernels ----------------
__global__ void detect_kernel(const unsigned* __restrict__ u) {
    unsigned v = 0;
    for (int k = threadIdx.x; k < 64; k += 32) v |= u[2 * k + 1];
#pragma unroll
    for (int o = 16; o; o >>= 1) v |= __shfl_xor_sync(0xffffffffu, v, o);
    if (threadIdx.x == 0) g_is64 = (v == 0) ? 1 : 0;
}

__global__ void zero_kernel(int aggCount) {
    const int stride = gridDim.x * blockDim.x;
    const int t0 = blockIdx.x * blockDim.x + threadIdx.x;
    for (int j = t0; j < aggCount; j += stride) g_agg[j] = 0.f;
    if (t0 < 2 * FF) g_stats1[t0] = 0.f;
    if (t0 < 2 * HN) g_stats2[t0] = 0.f;
}

// B pack (unchanged from R8)
__global__ void prepW_kernel(const float* __restrict__ W1) {
    const int gid = blockIdx.x * blockDim.x + threadIdx.x;
    if (gid >= 16384) return;
    const int lane = gid & 31, nt = (gid >> 5) & 3, wn = (gid >> 7) & 3;
    const int ks = (gid >> 9) & 7, hf = (gid >> 12) & 1, mode = gid >> 13;
    const int n = hf * 128 + wn * 32 + nt * 8 + (lane >> 2);
    const int k = ks * 16 + (lane & 3) * 2 + mode * HN;
    uint2 o;
    o.x = h2u(__floats2half2_rn(W1[(size_t)k * FF + n], W1[(size_t)(k + 1) * FF + n]));
    o.y = h2u(__floats2half2_rn(W1[(size_t)(k + 8) * FF + n], W1[(size_t)(k + 9) * FF + n]));
    g_Wt16[mode][hf][gid & 4095] = o;
}

// ---------------- sync-free fp16 warp-mma GEMM, direct fp32 A loads --------
// MODE 0: g_P (fp32) = node_emb @ W_top + b1
// MODE 1: g_h16 (fp16) = edge_emb @ W_bot + g_P[i[row]]  (+ fused BN1 stats)
// Job j: tile=j>>1, half=j&1 (grid even => half==blockIdx.x&1 constant per CTA).
// 8 warps: wm=wid&1 (rows wm*64+[0,64)), wn=wid>>1 (local cols wn*32+[0,32)).
template <int MODE>
__global__ __launch_bounds__(256, 2) void mma_gemm(
    const float* __restrict__ A, const float* __restrict__ b1,
    const void* __restrict__ ibuf, void* __restrict__ outv, int M)
{
    __shared__ uint2 Bs[4096];
    __shared__ float sstat[256];

    const int tid = threadIdx.x, lane = tid & 31, wid = tid >> 5;
    const int wm = wid & 1, wn = wid >> 1;
    const int ntiles = (M + 127) >> 7;
    const long long njobs = (long long)ntiles * 2;
    const int G = gridDim.x;
    const int halfc = blockIdx.x & 1;
    const int is64 = (MODE == 1) ? g_is64 : 0;

    {   // B pack -> smem, once
        const uint4* src = (const uint4*)&g_Wt16[MODE][halfc][0];
        uint4* dstv = (uint4*)Bs;
        for (int i = tid; i < 2048; i += 256) dstv[i] = src[i];
    }
    if (MODE == 1) sstat[tid] = 0.f;
    __syncthreads();

    float acc[4][4][4];
#pragma unroll
    for (int mt = 0; mt < 4; mt++)
#pragma unroll
        for (int nt = 0; nt < 4; nt++)
#pragma unroll
            for (int r = 0; r < 4; r++) acc[mt][nt][r] = 0.f;

    const int lq = (lane & 3) * 2;      // col pair base within 16-col k-step
    const int lr = lane >> 2;           // row within 8-row group

    for (long long job = blockIdx.x; job < njobs; job += G) {
        const long long tile = job >> 1;
        const long long rbase = tile << 7;

        // per-fragment row pointers (clamped: OOB rows read row M-1, discarded)
        const float* pr[4][2];
#pragma unroll
        for (int mt = 0; mt < 4; mt++) {
            long long r0 = rbase + wm * 64 + mt * 16 + lr;
            long long r1 = r0 + 8;
            if (r0 >= M) r0 = M - 1;
            if (r1 >= M) r1 = M - 1;
            pr[mt][0] = A + r0 * HN + lq;
            pr[mt][1] = A + r1 * HN + lq;
        }

        // ---- mainloop: no barriers, load+pack+mma, fully unrolled ----
#pragma unroll
        for (int ks = 0; ks < 8; ks++) {
            const int co = ks * 16;
            uint2 bfr[4];
#pragma unroll
            for (int nt = 0; nt < 4; nt++)
                bfr[nt] = Bs[(ks * 16 + wn * 4 + nt) * 32 + lane];
#pragma unroll
            for (int mt = 0; mt < 4; mt++) {
                const float2 v00 = *(const float2*)(pr[mt][0] + co);
                const float2 v10 = *(const float2*)(pr[mt][1] + co);
                const float2 v01 = *(const float2*)(pr[mt][0] + co + 8);
                const float2 v11 = *(const float2*)(pr[mt][1] + co + 8);
                uint4 a;
                a.x = h2u(__floats2half2_rn(v00.x, v00.y));
                a.y = h2u(__floats2half2_rn(v10.x, v10.y));
                a.z = h2u(__floats2half2_rn(v01.x, v01.y));
                a.w = h2u(__floats2half2_rn(v11.x, v11.y));
#pragma unroll
                for (int nt = 0; nt < 4; nt++)
                    mma16(acc[mt][nt], a, bfr[nt]);
            }
        }

        // ---- epilogue (identical to R8) ----
        float s[4][2], q[4][2];
        if (MODE == 1) {
#pragma unroll
            for (int nt = 0; nt < 4; nt++) {
                s[nt][0] = s[nt][1] = 0.f; q[nt][0] = q[nt][1] = 0.f;
            }
        }
#pragma unroll
        for (int mt = 0; mt < 4; mt++) {
            long long pb[2]; bool valid[2]; long long rown[2];
#pragma unroll
            for (int h = 0; h < 2; h++) {
                const long long row = rbase + wm * 64 + mt * 16 + lr + h * 8;
                rown[h] = row;
                valid[h] = row < (long long)M;
                pb[h] = 0;
                if (MODE == 1 && valid[h]) {
                    const long long idx = is64 ? ((const long long*)ibuf)[row]
                                               : (long long)((const int*)ibuf)[row];
                    pb[h] = idx * FF;
                }
            }
#pragma unroll
            for (int nt = 0; nt < 4; nt++) {
                const int c0 = halfc * 128 + wn * 32 + nt * 8 + lq;
#pragma unroll
                for (int h = 0; h < 2; h++) {
                    if (!valid[h]) continue;
                    float2 add;
                    if (MODE == 0) add = *(const float2*)(b1 + c0);
                    else           add = *(const float2*)(g_P + pb[h] + c0);
                    float2 o;
                    o.x = acc[mt][nt][2 * h] + add.x;
                    o.y = acc[mt][nt][2 * h + 1] + add.y;
                    if (MODE == 0) {
                        *(float2*)((float*)outv + rown[h] * FF + c0) = o;
                    } else {
                        *(__half2*)((__half*)outv + rown[h] * FF + c0) =
                            __floats2half2_rn(o.x, o.y);
                        s[nt][0] += o.x; q[nt][0] = fmaf(o.x, o.x, q[nt][0]);
                        s[nt][1] += o.y; q[nt][1] = fmaf(o.y, o.y, q[nt][1]);
                    }
                }
                acc[mt][nt][0] = 0.f; acc[mt][nt][1] = 0.f;
                acc[mt][nt][2] = 0.f; acc[mt][nt][3] = 0.f;
            }
        }
        if (MODE == 1) {
#pragma unroll
            for (int o = 4; o < 32; o <<= 1) {
#pragma unroll
                for (int nt = 0; nt < 4; nt++) {
                    s[nt][0] += __shfl_xor_sync(0xffffffffu, s[nt][0], o);
                    s[nt][1] += __shfl_xor_sync(0xffffffffu, s[nt][1], o);
                    q[nt][0] += __shfl_xor_sync(0xffffffffu, q[nt][0], o);
                    q[nt][1] += __shfl_xor_sync(0xffffffffu, q[nt][1], o);
                }
            }
            if (lane < 4) {
#pragma unroll
                for (int nt = 0; nt < 4; nt++) {
                    const int lc = wn * 32 + nt * 8 + 2 * lane;
                    atomicAdd(&sstat[lc], s[nt][0]);
                    atomicAdd(&sstat[lc + 1], s[nt][1]);
                    atomicAdd(&sstat[128 + lc], q[nt][0]);
                    atomicAdd(&sstat[128 + lc + 1], q[nt][1]);
                }
            }
        }
    }
    if (MODE == 1) {
        __syncthreads();
        if (tid < 128) {
            atomicAdd(&g_stats1[halfc * 128 + tid], sstat[tid]);
            atomicAdd(&g_stats1[256 + halfc * 128 + tid], sstat[128 + tid]);
        }
    }
}

// ---------------- BN1 finalize ----------------
__global__ void finalize1_kernel(const float* __restrict__ gamma1,
                                 const float* __restrict__ beta1, float invE) {
    const int j = threadIdx.x;
    const float mu  = g_stats1[j] * invE;
    const float var = g_stats1[FF + j] * invE - mu * mu;
    const float s   = gamma1[j] * rsqrtf(var + EPS);
    g_scale[j] = s;
    g_shift[j] = beta1[j] - mu * s;
}

// ---------------- gate + scatter (fp16 h, vector atomics; R8 form) --------
__global__ void gate_scatter_kernel(const void* __restrict__ ibuf, int E) {
    __shared__ float ssc[FF], ssh[FF];
    ssc[threadIdx.x] = g_scale[threadIdx.x];
    ssh[threadIdx.x] = g_shift[threadIdx.x];
    __syncthreads();
    const int is64 = g_is64;
    const long long total  = (long long)E * 32;
    const long long stride = (long long)gridDim.x * blockDim.x;
    for (long long t = (long long)blockIdx.x * blockDim.x + threadIdx.x;
         t < total; t += stride) {
        const long long e = t >> 5;
        const int c4 = (int)(t & 31) << 2;
        const __half* hrow = g_h16 + e * FF;
        const __half2 f01 = *(const __half2*)(hrow + c4);
        const __half2 f23 = *(const __half2*)(hrow + c4 + 2);
        const __half2 g01 = *(const __half2*)(hrow + HN + c4);
        const __half2 g23 = *(const __half2*)(hrow + HN + c4 + 2);
        const float2 fa = __half22float2(f01), fb = __half22float2(f23);
        const float2 ga = __half22float2(g01), gb = __half22float2(g23);
        float4 m;
        m.x = sigmoidf_(fa.x * ssc[c4 + 0] + ssh[c4 + 0]) * tanhf_(ga.x * ssc[HN + c4 + 0] + ssh[HN + c4 + 0]);
        m.y = sigmoidf_(fa.y * ssc[c4 + 1] + ssh[c4 + 1]) * tanhf_(ga.y * ssc[HN + c4 + 1] + ssh[HN + c4 + 1]);
        m.z = sigmoidf_(fb.x * ssc[c4 + 2] + ssh[c4 + 2]) * tanhf_(gb.x * ssc[HN + c4 + 2] + ssh[HN + c4 + 2]);
        m.w = sigmoidf_(fb.y * ssc[c4 + 3] + ssh[c4 + 3]) * tanhf_(gb.y * ssc[HN + c4 + 3] + ssh[HN + c4 + 3]);
        const long long idx = is64 ? ((const long long*)ibuf)[e]
                                   : (long long)((const int*)ibuf)[e];
        float* dst = g_agg + idx * HN + c4;
        asm volatile("red.global.add.v4.f32 [%0], {%1, %2, %3, %4};"
                     :: "l"(dst), "f"(m.x), "f"(m.y), "f"(m.z), "f"(m.w) : "memory");
    }
}

// ---------------- BN2 + final ----------------
__global__ void stats2_kernel(int N) {
    const int t = blockIdx.x * blockDim.x + threadIdx.x;
    const int col = t & (HN - 1);
    const int r0 = t >> 7;
    const int rs = (gridDim.x * blockDim.x) >> 7;
    float s = 0.f, sq = 0.f;
    for (long long r = r0; r < N; r += rs) {
        const float v = g_agg[r * HN + col];
        s += v; sq = fmaf(v, v, sq);
    }
    atomicAdd(&g_stats2[col], s);
    atomicAdd(&g_stats2[HN + col], sq);
}

__global__ void final_kernel(const float* __restrict__ node_emb,
                             const float* __restrict__ gamma2,
                             const float* __restrict__ beta2,
                             float* __restrict__ out, int total, float invN) {
    const int t = blockIdx.x * blockDim.x + threadIdx.x;
    if (t >= total) return;
    const int col = t & (HN - 1);
    const float mu  = g_stats2[col] * invN;
    const float var = g_stats2[HN + col] * invN - mu * mu;
    const float c1  = (g_agg[t] - mu) * rsqrtf(var + EPS) * gamma2[col] + beta2[col];
    out[t] = tanhf_(node_emb[t] + c1);
}

// ---------------- launch ----------------
extern "C" void kernel_launch(void* const* d_in, const int* in_sizes, int n_in,
                              void* d_out, int out_size) {
    const float* node_emb = (const float*)d_in[0];
    const float* edge_emb = (const float*)d_in[1];
    const void*  ibuf     = d_in[2];
    const float* W1       = (const float*)d_in[3];
    const float* b1       = (const float*)d_in[4];
    const float* gamma1   = (const float*)d_in[5];
    const float* beta1    = (const float*)d_in[6];
    const float* gamma2   = (const float*)d_in[7];
    const float* beta2    = (const float*)d_in[8];
    float* out = (float*)d_out;

    const int N = in_sizes[0] / HN;
    const int E = in_sizes[1] / HN;

    float*  g_P_ptr;  cudaGetSymbolAddress((void**)&g_P_ptr, g_P);
    __half* g_h_ptr;  cudaGetSymbolAddress((void**)&g_h_ptr, g_h16);

    detect_kernel<<<1, 32>>>((const unsigned*)ibuf);
    zero_kernel<<<4096, 256>>>(N * HN);
    prepW_kernel<<<64, 256>>>(W1);

    mma_gemm<0><<<296, 256>>>(node_emb, b1, ibuf, g_P_ptr, N);
    mma_gemm<1><<<296, 256>>>(edge_emb, b1, ibuf, g_h_ptr, E);

    finalize1_kernel<<<1, 256>>>(gamma1, beta1, 1.0f / (float)E);
    gate_scatter_kernel<<<8192, 256>>>(ibuf, E);

    stats2_kernel<<<1024, 256>>>(N);
    final_kernel<<<(N * HN + 255) / 256, 256>>>(node_emb, gamma2, beta2, out,
                                                N * HN, 1.0f / (float)N);
}

// round 11
// speedup vs baseline: 1.2149x; 1.2149x over previous
#include <cuda_runtime.h>
#include <cuda_fp16.h>
#include <cstdint>

#define HN 128
#define FF 256
#define NMAX 50048
#define EMAX 800000
#define EPS 1e-5f
#define NBLK_N (NMAX / 64)    // 782
#define NBLK_E (EMAX / 64)    // 12500

// ---------------- static scratch ----------------
__device__ float  g_P[(size_t)NMAX * FF];
__device__ __half g_h16[(size_t)EMAX * FF];
__device__ float  g_agg[(size_t)NMAX * HN];
__device__ uint4  g_Ae[(size_t)NBLK_E * 1024];   // edge A, fp16 frag-packed
__device__ uint4  g_An[(size_t)NBLK_N * 1024];   // node A, fp16 frag-packed
__device__ uint2  g_Wt16[2][2][4096];            // [mode][half] B fp16 frag-packed
__device__ float  g_stats1[2 * FF];
__device__ float  g_stats2[2 * HN];
__device__ float  g_scale[FF];
__device__ float  g_shift[FF];
__device__ int    g_is64;

// ---------------- helpers ----------------
__device__ __forceinline__ float tanhf_(float x) {      // exact-ish (final output)
    float t = __expf(2.f * x);
    return 1.f - __fdividef(2.f, t + 1.f);
}
__device__ __forceinline__ float tanha(float x) {       // 1 MUFU
    float y; asm("tanh.approx.f32 %0, %1;" : "=f"(y) : "f"(x)); return y;
}
__device__ __forceinline__ float sigmoida(float x) {    // 1 MUFU + 1 FMA
    return fmaf(tanha(x * 0.5f), 0.5f, 0.5f);
}
__device__ __forceinline__ void mma16(float* c, const uint4 a, const uint2 b) {
    asm volatile("mma.sync.aligned.m16n8k16.row.col.f32.f16.f16.f32 "
                 "{%0,%1,%2,%3},{%4,%5,%6,%7},{%8,%9},{%0,%1,%2,%3};"
                 : "+f"(c[0]), "+f"(c[1]), "+f"(c[2]), "+f"(c[3])
                 : "r"(a.x), "r"(a.y), "r"(a.z), "r"(a.w), "r"(b.x), "r"(b.y));
}
__device__ __forceinline__ uint32_t h2u(__half2 h) {
    return *reinterpret_cast<uint32_t*>(&h);
}

// ---------------- small kernels ----------------
__global__ void detect_kernel(const unsigned* __restrict__ u) {
    unsigned v = 0;
    for (int k = threadIdx.x; k < 64; k += 32) v |= u[2 * k + 1];
#pragma unroll
    for (int o = 16; o; o >>= 1) v |= __shfl_xor_sync(0xffffffffu, v, o);
    if (threadIdx.x == 0) g_is64 = (v == 0) ? 1 : 0;
}

__global__ void zero_kernel(int aggCount) {
    const int stride = gridDim.x * blockDim.x;
    const int t0 = blockIdx.x * blockDim.x + threadIdx.x;
    for (int j = t0; j < aggCount; j += stride) g_agg[j] = 0.f;
    if (t0 < 2 * FF) g_stats1[t0] = 0.f;
    if (t0 < 2 * HN) g_stats2[t0] = 0.f;
}

// A pack (R8): unit gid = ((block*8 + ks)*4 + mt)*32 + lane -> one uint4
__global__ void prepA_kernel(const float* __restrict__ A, uint4* __restrict__ dst,
                             int M, int nunits) {
    const int gid = blockIdx.x * blockDim.x + threadIdx.x;
    if (gid >= nunits) return;
    const int lane = gid & 31, mt = (gid >> 5) & 3, ks = (gid >> 7) & 7;
    const int block = gid >> 10;
    const int r0 = block * 64 + mt * 16 + (lane >> 2);
    const int r1 = r0 + 8;
    const int c0 = ks * 16 + (lane & 3) * 2;
    float2 v00 = make_float2(0.f, 0.f), v01 = v00, v10 = v00, v11 = v00;
    if (r0 < M) {
        v00 = *(const float2*)(A + (size_t)r0 * HN + c0);
        v01 = *(const float2*)(A + (size_t)r0 * HN + c0 + 8);
    }
    if (r1 < M) {
        v10 = *(const float2*)(A + (size_t)r1 * HN + c0);
        v11 = *(const float2*)(A + (size_t)r1 * HN + c0 + 8);
    }
    uint4 o;
    o.x = h2u(__floats2half2_rn(v00.x, v00.y));
    o.y = h2u(__floats2half2_rn(v10.x, v10.y));
    o.z = h2u(__floats2half2_rn(v01.x, v01.y));
    o.w = h2u(__floats2half2_rn(v11.x, v11.y));
    dst[gid] = o;
}

// B pack (R8)
__global__ void prepW_kernel(const float* __restrict__ W1) {
    const int gid = blockIdx.x * blockDim.x + threadIdx.x;
    if (gid >= 16384) return;
    const int lane = gid & 31, nt = (gid >> 5) & 3, wn = (gid >> 7) & 3;
    const int ks = (gid >> 9) & 7, hf = (gid >> 12) & 1, mode = gid >> 13;
    const int n = hf * 128 + wn * 32 + nt * 8 + (lane >> 2);
    const int k = ks * 16 + (lane & 3) * 2 + mode * HN;
    uint2 o;
    o.x = h2u(__floats2half2_rn(W1[(size_t)k * FF + n], W1[(size_t)(k + 1) * FF + n]));
    o.y = h2u(__floats2half2_rn(W1[(size_t)(k + 8) * FF + n], W1[(size_t)(k + 9) * FF + n]));
    g_Wt16[mode][hf][gid & 4095] = o;
}

// ---------------- sync-free fp16 warp-mma GEMM (exact R8 structure) --------
template <int MODE>
__global__ __launch_bounds__(256, 2) void mma_gemm(
    const uint4* __restrict__ Apk, const float* __restrict__ b1,
    const void* __restrict__ ibuf, void* __restrict__ outv, int M)
{
    __shared__ uint2 Bs[4096];
    __shared__ float sstat[256];

    const int tid = threadIdx.x, lane = tid & 31, wid = tid >> 5;
    const int wm = wid & 1, wn = wid >> 1;
    const int ntiles = (M + 127) >> 7;
    const long long njobs = (long long)ntiles * 2;
    const int G = gridDim.x;
    const int halfc = blockIdx.x & 1;
    const int is64 = (MODE == 1) ? g_is64 : 0;

    {   // B pack -> smem, once
        const uint4* src = (const uint4*)&g_Wt16[MODE][halfc][0];
        uint4* dstv = (uint4*)Bs;
        for (int i = tid; i < 2048; i += 256) dstv[i] = src[i];
    }
    if (MODE == 1) sstat[tid] = 0.f;
    __syncthreads();

    float acc[4][4][4];
#pragma unroll
    for (int mt = 0; mt < 4; mt++)
#pragma unroll
        for (int nt = 0; nt < 4; nt++)
#pragma unroll
            for (int r = 0; r < 4; r++) acc[mt][nt][r] = 0.f;

    for (long long job = blockIdx.x; job < njobs; job += G) {
        const long long tile = job >> 1;
        const uint4* abase = Apk + ((tile * 2 + wm) << 10);

        // ---- mainloop: no barriers, A double-buffered in regs ----
        uint4 acur[4], anxt[4];
#pragma unroll
        for (int mt = 0; mt < 4; mt++) acur[mt] = abase[mt * 32 + lane];
#pragma unroll
        for (int ks = 0; ks < 8; ks++) {
            uint2 bfr[4];
#pragma unroll
            for (int nt = 0; nt < 4; nt++)
                bfr[nt] = Bs[(ks * 16 + wn * 4 + nt) * 32 + lane];
            if (ks < 7) {
#pragma unroll
                for (int mt = 0; mt < 4; mt++)
                    anxt[mt] = abase[(ks + 1) * 128 + mt * 32 + lane];
            }
#pragma unroll
            for (int mt = 0; mt < 4; mt++)
#pragma unroll
                for (int nt = 0; nt < 4; nt++)
                    mma16(acc[mt][nt], acur[mt], bfr[nt]);
#pragma unroll
            for (int mt = 0; mt < 4; mt++) acur[mt] = anxt[mt];
        }

        // ---- epilogue ----
        const long long rbase = tile << 7;
        float s[4][2], q[4][2];
        if (MODE == 1) {
#pragma unroll
            for (int nt = 0; nt < 4; nt++) {
                s[nt][0] = s[nt][1] = 0.f; q[nt][0] = q[nt][1] = 0.f;
            }
        }
#pragma unroll
        for (int mt = 0; mt < 4; mt++) {
            long long pb[2]; bool valid[2]; long long rown[2];
#pragma unroll
            for (int h = 0; h < 2; h++) {
                const long long row = rbase + wm * 64 + mt * 16 + (lane >> 2) + h * 8;
                rown[h] = row;
                valid[h] = row < (long long)M;
                pb[h] = 0;
                if (MODE == 1 && valid[h]) {
                    const long long idx = is64 ? ((const long long*)ibuf)[row]
                                               : (long long)((const int*)ibuf)[row];
                    pb[h] = idx * FF;
                }
            }
#pragma unroll
            for (int nt = 0; nt < 4; nt++) {
                const int c0 = halfc * 128 + wn * 32 + nt * 8 + 2 * (lane & 3);
#pragma unroll
                for (int h = 0; h < 2; h++) {
                    if (!valid[h]) continue;
                    float2 add;
                    if (MODE == 0) add = *(const float2*)(b1 + c0);
                    else           add = *(const float2*)(g_P + pb[h] + c0);
                    float2 o;
                    o.x = acc[mt][nt][2 * h] + add.x;
                    o.y = acc[mt][nt][2 * h + 1] + add.y;
                    if (MODE == 0) {
                        *(float2*)((float*)outv + rown[h] * FF + c0) = o;
                    } else {
                        *(__half2*)((__half*)outv + rown[h] * FF + c0) =
                            __floats2half2_rn(o.x, o.y);
                        s[nt][0] += o.x; q[nt][0] = fmaf(o.x, o.x, q[nt][0]);
                        s[nt][1] += o.y; q[nt][1] = fmaf(o.y, o.y, q[nt][1]);
                    }
                }
                acc[mt][nt][0] = 0.f; acc[mt][nt][1] = 0.f;
                acc[mt][nt][2] = 0.f; acc[mt][nt][3] = 0.f;
            }
        }
        if (MODE == 1) {
#pragma unroll
            for (int o = 4; o < 32; o <<= 1) {
#pragma unroll
                for (int nt = 0; nt < 4; nt++) {
                    s[nt][0] += __shfl_xor_sync(0xffffffffu, s[nt][0], o);
                    s[nt][1] += __shfl_xor_sync(0xffffffffu, s[nt][1], o);
                    q[nt][0] += __shfl_xor_sync(0xffffffffu, q[nt][0], o);
                    q[nt][1] += __shfl_xor_sync(0xffffffffu, q[nt][1], o);
                }
            }
            if (lane < 4) {
#pragma unroll
                for (int nt = 0; nt < 4; nt++) {
                    const int lc = wn * 32 + nt * 8 + 2 * lane;
                    atomicAdd(&sstat[lc], s[nt][0]);
                    atomicAdd(&sstat[lc + 1], s[nt][1]);
                    atomicAdd(&sstat[128 + lc], q[nt][0]);
                    atomicAdd(&sstat[128 + lc + 1], q[nt][1]);
                }
            }
        }
    }
    if (MODE == 1) {
        __syncthreads();
        if (tid < 128) {
            atomicAdd(&g_stats1[halfc * 128 + tid], sstat[tid]);
            atomicAdd(&g_stats1[256 + halfc * 128 + tid], sstat[128 + tid]);
        }
    }
}

// ---------------- BN1 finalize ----------------
__global__ void finalize1_kernel(const float* __restrict__ gamma1,
                                 const float* __restrict__ beta1, float invE) {
    const int j = threadIdx.x;
    const float mu  = g_stats1[j] * invE;
    const float var = g_stats1[FF + j] * invE - mu * mu;
    const float s   = gamma1[j] * rsqrtf(var + EPS);
    g_scale[j] = s;
    g_shift[j] = beta1[j] - mu * s;
}

// ---------------- gate + scatter: 8 cols/thread, tanh.approx ----------------
__global__ void gate_scatter_kernel(const void* __restrict__ ibuf, int E) {
    __shared__ float ssc[FF], ssh[FF];
    ssc[threadIdx.x] = g_scale[threadIdx.x];
    ssh[threadIdx.x] = g_shift[threadIdx.x];
    __syncthreads();
    const int is64 = g_is64;
    const long long total  = (long long)E * 16;
    const long long stride = (long long)gridDim.x * blockDim.x;
    for (long long t = (long long)blockIdx.x * blockDim.x + threadIdx.x;
         t < total; t += stride) {
        const long long e = t >> 4;
        const int c8 = (int)(t & 15) << 3;
        const __half* hrow = g_h16 + e * FF;
        const uint4 fv = *(const uint4*)(hrow + c8);        // 8 halves (filter)
        const uint4 gv = *(const uint4*)(hrow + HN + c8);   // 8 halves (core)
        const long long idx = is64 ? ((const long long*)ibuf)[e]
                                   : (long long)((const int*)ibuf)[e];
        float* dst = g_agg + idx * HN + c8;
        float m[8];
#pragma unroll
        for (int p = 0; p < 4; p++) {
            const float2 f2 = __half22float2(*(((const __half2*)&fv) + p));
            const float2 g2 = __half22float2(*(((const __half2*)&gv) + p));
            const int c = c8 + 2 * p;
            m[2 * p]     = sigmoida(f2.x * ssc[c]     + ssh[c])     * tanha(g2.x * ssc[HN + c]     + ssh[HN + c]);
            m[2 * p + 1] = sigmoida(f2.y * ssc[c + 1] + ssh[c + 1]) * tanha(g2.y * ssc[HN + c + 1] + ssh[HN + c + 1]);
        }
        asm volatile("red.global.add.v4.f32 [%0], {%1, %2, %3, %4};"
                     :: "l"(dst), "f"(m[0]), "f"(m[1]), "f"(m[2]), "f"(m[3]) : "memory");
        asm volatile("red.global.add.v4.f32 [%0], {%1, %2, %3, %4};"
                     :: "l"(dst + 4), "f"(m[4]), "f"(m[5]), "f"(m[6]), "f"(m[7]) : "memory");
    }
}

// ---------------- BN2 + final ----------------
__global__ void stats2_kernel(int N) {
    const int t = blockIdx.x * blockDim.x + threadIdx.x;
    const int col = t & (HN - 1);
    const int r0 = t >> 7;
    const int rs = (gridDim.x * blockDim.x) >> 7;
    float s = 0.f, sq = 0.f;
    for (long long r = r0; r < N; r += rs) {
        const float v = g_agg[r * HN + col];
        s += v; sq = fmaf(v, v, sq);
    }
    atomicAdd(&g_stats2[col], s);
    atomicAdd(&g_stats2[HN + col], sq);
}

__global__ void final_kernel(const float* __restrict__ node_emb,
                             const float* __restrict__ gamma2,
                             const float* __restrict__ beta2,
                             float* __restrict__ out, int total, float invN) {
    const int t = blockIdx.x * blockDim.x + threadIdx.x;
    if (t >= total) return;
    const int col = t & (HN - 1);
    const float mu  = g_stats2[col] * invN;
    const float var = g_stats2[HN + col] * invN - mu * mu;
    const float c1  = (g_agg[t] - mu) * rsqrtf(var + EPS) * gamma2[col] + beta2[col];
    out[t] = tanhf_(node_emb[t] + c1);
}

// ---------------- launch ----------------
extern "C" void kernel_launch(void* const* d_in, const int* in_sizes, int n_in,
                              void* d_out, int out_size) {
    const float* node_emb = (const float*)d_in[0];
    const float* edge_emb = (const float*)d_in[1];
    const void*  ibuf     = d_in[2];
    const float* W1       = (const float*)d_in[3];
    const float* b1       = (const float*)d_in[4];
    const float* gamma1   = (const float*)d_in[5];
    const float* beta1    = (const float*)d_in[6];
    const float* gamma2   = (const float*)d_in[7];
    const float* beta2    = (const float*)d_in[8];
    float* out = (float*)d_out;

    const int N = in_sizes[0] / HN;
    const int E = in_sizes[1] / HN;

    float*  g_P_ptr;  cudaGetSymbolAddress((void**)&g_P_ptr, g_P);
    __half* g_h_ptr;  cudaGetSymbolAddress((void**)&g_h_ptr, g_h16);
    uint4*  g_Ae_ptr; cudaGetSymbolAddress((void**)&g_Ae_ptr, g_Ae);
    uint4*  g_An_ptr; cudaGetSymbolAddress((void**)&g_An_ptr, g_An);

    detect_kernel<<<1, 32>>>((const unsigned*)ibuf);
    zero_kernel<<<4096, 256>>>(N * HN);
    prepW_kernel<<<64, 256>>>(W1);

    const int unitsN = NBLK_N * 1024;
    const int unitsE = NBLK_E * 1024;
    prepA_kernel<<<(unitsN + 255) / 256, 256>>>(node_emb, g_An_ptr, N, unitsN);
    prepA_kernel<<<(unitsE + 255) / 256, 256>>>(edge_emb, g_Ae_ptr, E, unitsE);

    mma_gemm<0><<<296, 256>>>(g_An_ptr, b1, ibuf, g_P_ptr, N);
    mma_gemm<1><<<296, 256>>>(g_Ae_ptr, b1, ibuf, g_h_ptr, E);

    finalize1_kernel<<<1, 256>>>(gamma1, beta1, 1.0f / (float)E);
    gate_scatter_kernel<<<8192, 256>>>(ibuf, E);

    stats2_kernel<<<1024, 256>>>(N);
    final_kernel<<<(N * HN + 255) / 256, 256>>>(node_emb, gamma2, beta2, out,
                                                N * HN, 1.0f / (float)N);
}

// round 12
// speedup vs baseline: 1.2834x; 1.0564x over previous
#include <cuda_runtime.h>
#include <cuda_fp16.h>
#include <cstdint>

#define HN 128
#define FF 256
#define NMAX 50048
#define EMAX 800000
#define EPS 1e-5f
#define NBLK_N (NMAX / 64)    // 782
#define NBLK_E (EMAX / 64)    // 12500
#define DEPTH 4

// ---------------- static scratch ----------------
__device__ float  g_P[(size_t)NMAX * FF];
__device__ __half g_h16[(size_t)EMAX * FF];
__device__ float  g_agg[(size_t)NMAX * HN];
__device__ uint4  g_Ae[(size_t)NBLK_E * 1024];   // edge A, fp16 frag-packed
__device__ uint4  g_An[(size_t)NBLK_N * 1024];   // node A, fp16 frag-packed
__device__ uint2  g_Wt16[2][2][4096];            // [mode][half] B fp16 frag-packed
__device__ float  g_stats1[2 * FF];
__device__ float  g_stats2[2 * HN];
__device__ float  g_scale[FF];
__device__ float  g_shift[FF];
__device__ int    g_is64;

// ---------------- helpers ----------------
__device__ __forceinline__ uint32_t smem_u32(const void* p) {
    uint32_t a;
    asm("{ .reg .u64 t; cvta.to.shared.u64 t, %1; cvt.u32.u64 %0, t; }" : "=r"(a) : "l"(p));
    return a;
}
__device__ __forceinline__ float tanhf_(float x) {      // exact-ish (final output)
    float t = __expf(2.f * x);
    return 1.f - __fdividef(2.f, t + 1.f);
}
__device__ __forceinline__ float tanha(float x) {       // 1 MUFU
    float y; asm("tanh.approx.f32 %0, %1;" : "=f"(y) : "f"(x)); return y;
}
__device__ __forceinline__ float sigmoida(float x) {    // 1 MUFU + 1 FMA
    return fmaf(tanha(x * 0.5f), 0.5f, 0.5f);
}
__device__ __forceinline__ void mma16(float* c, const uint4 a, const uint2 b) {
    asm volatile("mma.sync.aligned.m16n8k16.row.col.f32.f16.f16.f32 "
                 "{%0,%1,%2,%3},{%4,%5,%6,%7},{%8,%9},{%0,%1,%2,%3};"
                 : "+f"(c[0]), "+f"(c[1]), "+f"(c[2]), "+f"(c[3])
                 : "r"(a.x), "r"(a.y), "r"(a.z), "r"(a.w), "r"(b.x), "r"(b.y));
}
__device__ __forceinline__ uint32_t h2u(__half2 h) {
    return *reinterpret_cast<uint32_t*>(&h);
}
__device__ __forceinline__ void cpasync16(uint32_t dst, const void* src) {
    asm volatile("cp.async.cg.shared.global [%0], [%1], 16;"
                 :: "r"(dst), "l"(src) : "memory");
}
#define CP_COMMIT() asm volatile("cp.async.commit_group;" ::: "memory")
__device__ __forceinline__ void cp_wait(int n) {        // n is compile-time const
    if (n == 0)      asm volatile("cp.async.wait_group 0;" ::: "memory");
    else if (n == 1) asm volatile("cp.async.wait_group 1;" ::: "memory");
    else if (n == 2) asm volatile("cp.async.wait_group 2;" ::: "memory");
    else             asm volatile("cp.async.wait_group 3;" ::: "memory");
}
__device__ __forceinline__ void lds128(uint4& r, uint32_t addr) {
    asm volatile("ld.shared.v4.u32 {%0,%1,%2,%3}, [%4];"
                 : "=r"(r.x), "=r"(r.y), "=r"(r.z), "=r"(r.w) : "r"(addr));
}

// SMEM map (bytes): Bs 32KB | abuf 8 warps x 8KB | sstat 1KB = 99328 (2 CTAs/SM)
#define ABUF_OFF  32768
#define SSTAT_OFF 98304
#define SMEM_SZ   99328

// ---------------- small kernels ----------------
__global__ void detect_kernel(const unsigned* __restrict__ u) {
    unsigned v = 0;
    for (int k = threadIdx.x; k < 64; k += 32) v |= u[2 * k + 1];
#pragma unroll
    for (int o = 16; o; o >>= 1) v |= __shfl_xor_sync(0xffffffffu, v, o);
    if (threadIdx.x == 0) g_is64 = (v == 0) ? 1 : 0;
}

__global__ void zero_kernel(int aggCount) {
    const int stride = gridDim.x * blockDim.x;
    const int t0 = blockIdx.x * blockDim.x + threadIdx.x;
    for (int j = t0; j < aggCount; j += stride) g_agg[j] = 0.f;
    if (t0 < 2 * FF) g_stats1[t0] = 0.f;
    if (t0 < 2 * HN) g_stats2[t0] = 0.f;
}

// A pack (R8): unit gid = ((block*8 + ks)*4 + mt)*32 + lane -> one uint4
__global__ void prepA_kernel(const float* __restrict__ A, uint4* __restrict__ dst,
                             int M, int nunits) {
    const int gid = blockIdx.x * blockDim.x + threadIdx.x;
    if (gid >= nunits) return;
    const int lane = gid & 31, mt = (gid >> 5) & 3, ks = (gid >> 7) & 7;
    const int block = gid >> 10;
    const int r0 = block * 64 + mt * 16 + (lane >> 2);
    const int r1 = r0 + 8;
    const int c0 = ks * 16 + (lane & 3) * 2;
    float2 v00 = make_float2(0.f, 0.f), v01 = v00, v10 = v00, v11 = v00;
    if (r0 < M) {
        v00 = *(const float2*)(A + (size_t)r0 * HN + c0);
        v01 = *(const float2*)(A + (size_t)r0 * HN + c0 + 8);
    }
    if (r1 < M) {
        v10 = *(const float2*)(A + (size_t)r1 * HN + c0);
        v11 = *(const float2*)(A + (size_t)r1 * HN + c0 + 8);
    }
    uint4 o;
    o.x = h2u(__floats2half2_rn(v00.x, v00.y));
    o.y = h2u(__floats2half2_rn(v10.x, v10.y));
    o.z = h2u(__floats2half2_rn(v01.x, v01.y));
    o.w = h2u(__floats2half2_rn(v11.x, v11.y));
    dst[gid] = o;
}

// B pack (R8)
__global__ void prepW_kernel(const float* __restrict__ W1) {
    const int gid = blockIdx.x * blockDim.x + threadIdx.x;
    if (gid >= 16384) return;
    const int lane = gid & 31, nt = (gid >> 5) & 3, wn = (gid >> 7) & 3;
    const int ks = (gid >> 9) & 7, hf = (gid >> 12) & 1, mode = gid >> 13;
    const int n = hf * 128 + wn * 32 + nt * 8 + (lane >> 2);
    const int k = ks * 16 + (lane & 3) * 2 + mode * HN;
    uint2 o;
    o.x = h2u(__floats2half2_rn(W1[(size_t)k * FF + n], W1[(size_t)(k + 1) * FF + n]));
    o.y = h2u(__floats2half2_rn(W1[(size_t)(k + 8) * FF + n], W1[(size_t)(k + 9) * FF + n]));
    g_Wt16[mode][hf][gid & 4095] = o;
}

// ---------------- fp16 warp-mma GEMM, warp-private cp.async pipeline --------
// MODE 0: g_P (fp32) = node_emb @ W_top + b1
// MODE 1: g_h16 (fp16) = edge_emb @ W_bot + g_P[i[row]]  (+ fused BN1 stats)
// Job j: tile=j>>1, half=j&1 (grid even => half constant per CTA).
// Each lane cp.asyncs ITS OWN fragment slice and LDSes it back -> no barriers.
template <int MODE>
__global__ __launch_bounds__(256, 2) void mma_gemm(
    const uint4* __restrict__ Apk, const float* __restrict__ b1,
    const void* __restrict__ ibuf, void* __restrict__ outv, int M)
{
    extern __shared__ char smem[];
    uint2* Bs = (uint2*)smem;
    float* sstat = (float*)(smem + SSTAT_OFF);

    const int tid = threadIdx.x, lane = tid & 31, wid = tid >> 5;
    const int wm = wid & 1, wn = wid >> 1;
    const int ntiles = (M + 127) >> 7;
    const long long njobs = (long long)ntiles * 2;
    const int G = gridDim.x;
    const int halfc = blockIdx.x & 1;
    const int is64 = (MODE == 1) ? g_is64 : 0;

    // per-lane smem slot base (byte address): abuf[wid][slot][mt][lane]
    const uint32_t wbuf = smem_u32(smem) + ABUF_OFF + (uint32_t)wid * 8192
                          + (uint32_t)lane * 16;

    {   // B pack -> smem, once
        const uint4* src = (const uint4*)&g_Wt16[MODE][halfc][0];
        uint4* dstv = (uint4*)Bs;
        for (int i = tid; i < 2048; i += 256) dstv[i] = src[i];
    }
    if (MODE == 1) sstat[tid] = 0.f;
    __syncthreads();

    float acc[4][4][4];
#pragma unroll
    for (int mt = 0; mt < 4; mt++)
#pragma unroll
        for (int nt = 0; nt < 4; nt++)
#pragma unroll
            for (int r = 0; r < 4; r++) acc[mt][nt][r] = 0.f;

    for (long long job = blockIdx.x; job < njobs; job += G) {
        const long long tile = job >> 1;
        const uint4* abase = Apk + ((tile * 2 + wm) << 10) + lane;

        // ---- prologue: fill DEPTH pipeline stages (warp-private) ----
#pragma unroll
        for (int p = 0; p < DEPTH; p++) {
#pragma unroll
            for (int mt = 0; mt < 4; mt++)
                cpasync16(wbuf + (uint32_t)((p * 4 + mt) << 9),
                          abase + p * 128 + mt * 32);
            CP_COMMIT();
        }

        // ---- mainloop: no barriers ----
#pragma unroll
        for (int ks = 0; ks < 8; ks++) {
            const int wn_ = (7 - ks < DEPTH - 1) ? (7 - ks) : (DEPTH - 1);
            cp_wait(wn_);
            uint2 bfr[4];
#pragma unroll
            for (int nt = 0; nt < 4; nt++)
                bfr[nt] = Bs[(ks * 16 + wn * 4 + nt) * 32 + lane];
            uint4 a[4];
#pragma unroll
            for (int mt = 0; mt < 4; mt++)
                lds128(a[mt], wbuf + (uint32_t)((((ks % DEPTH) * 4) + mt) << 9));
            if (ks + DEPTH < 8) {
#pragma unroll
                for (int mt = 0; mt < 4; mt++)
                    cpasync16(wbuf + (uint32_t)(((((ks + DEPTH) % DEPTH) * 4) + mt) << 9),
                              abase + (ks + DEPTH) * 128 + mt * 32);
                CP_COMMIT();
            }
#pragma unroll
            for (int mt = 0; mt < 4; mt++)
#pragma unroll
                for (int nt = 0; nt < 4; nt++)
                    mma16(acc[mt][nt], a[mt], bfr[nt]);
        }

        // ---- epilogue (R8) ----
        const long long rbase = tile << 7;
        float s[4][2], q[4][2];
        if (MODE == 1) {
#pragma unroll
            for (int nt = 0; nt < 4; nt++) {
                s[nt][0] = s[nt][1] = 0.f; q[nt][0] = q[nt][1] = 0.f;
            }
        }
#pragma unroll
        for (int mt = 0; mt < 4; mt++) {
            long long pb[2]; bool valid[2]; long long rown[2];
#pragma unroll
            for (int h = 0; h < 2; h++) {
                const long long row = rbase + wm * 64 + mt * 16 + (lane >> 2) + h * 8;
                rown[h] = row;
                valid[h] = row < (long long)M;
                pb[h] = 0;
                if (MODE == 1 && valid[h]) {
                    const long long idx = is64 ? ((const long long*)ibuf)[row]
                                               : (long long)((const int*)ibuf)[row];
                    pb[h] = idx * FF;
                }
            }
#pragma unroll
            for (int nt = 0; nt < 4; nt++) {
                const int c0 = halfc * 128 + wn * 32 + nt * 8 + 2 * (lane & 3);
#pragma unroll
                for (int h = 0; h < 2; h++) {
                    if (!valid[h]) continue;
                    float2 add;
                    if (MODE == 0) add = *(const float2*)(b1 + c0);
                    else           add = *(const float2*)(g_P + pb[h] + c0);
                    float2 o;
                    o.x = acc[mt][nt][2 * h] + add.x;
                    o.y = acc[mt][nt][2 * h + 1] + add.y;
                    if (MODE == 0) {
                        *(float2*)((float*)outv + rown[h] * FF + c0) = o;
                    } else {
                        *(__half2*)((__half*)outv + rown[h] * FF + c0) =
                            __floats2half2_rn(o.x, o.y);
                        s[nt][0] += o.x; q[nt][0] = fmaf(o.x, o.x, q[nt][0]);
                        s[nt][1] += o.y; q[nt][1] = fmaf(o.y, o.y, q[nt][1]);
                    }
                }
                acc[mt][nt][0] = 0.f; acc[mt][nt][1] = 0.f;
                acc[mt][nt][2] = 0.f; acc[mt][nt][3] = 0.f;
            }
        }
        if (MODE == 1) {
#pragma unroll
            for (int o = 4; o < 32; o <<= 1) {
#pragma unroll
                for (int nt = 0; nt < 4; nt++) {
                    s[nt][0] += __shfl_xor_sync(0xffffffffu, s[nt][0], o);
                    s[nt][1] += __shfl_xor_sync(0xffffffffu, s[nt][1], o);
                    q[nt][0] += __shfl_xor_sync(0xffffffffu, q[nt][0], o);
                    q[nt][1] += __shfl_xor_sync(0xffffffffu, q[nt][1], o);
                }
            }
            if (lane < 4) {
#pragma unroll
                for (int nt = 0; nt < 4; nt++) {
                    const int lc = wn * 32 + nt * 8 + 2 * lane;
                    atomicAdd(&sstat[lc], s[nt][0]);
                    atomicAdd(&sstat[lc + 1], s[nt][1]);
                    atomicAdd(&sstat[128 + lc], q[nt][0]);
                    atomicAdd(&sstat[128 + lc + 1], q[nt][1]);
                }
            }
        }
    }
    if (MODE == 1) {
        __syncthreads();
        if (tid < 128) {
            atomicAdd(&g_stats1[halfc * 128 + tid], sstat[tid]);
            atomicAdd(&g_stats1[256 + halfc * 128 + tid], sstat[128 + tid]);
        }
    }
}

// ---------------- BN1 finalize ----------------
__global__ void finalize1_kernel(const float* __restrict__ gamma1,
                                 const float* __restrict__ beta1, float invE) {
    const int j = threadIdx.x;
    const float mu  = g_stats1[j] * invE;
    const float var = g_stats1[FF + j] * invE - mu * mu;
    const float s   = gamma1[j] * rsqrtf(var + EPS);
    g_scale[j] = s;
    g_shift[j] = beta1[j] - mu * s;
}

// ---------------- gate + scatter (R8 4-col shape, tanh.approx math) --------
__global__ void gate_scatter_kernel(const void* __restrict__ ibuf, int E) {
    __shared__ float ssc[FF], ssh[FF];
    ssc[threadIdx.x] = g_scale[threadIdx.x];
    ssh[threadIdx.x] = g_shift[threadIdx.x];
    __syncthreads();
    const int is64 = g_is64;
    const long long total  = (long long)E * 32;
    const long long stride = (long long)gridDim.x * blockDim.x;
    for (long long t = (long long)blockIdx.x * blockDim.x + threadIdx.x;
         t < total; t += stride) {
        const long long e = t >> 5;
        const int c4 = (int)(t & 31) << 2;
        const __half* hrow = g_h16 + e * FF;
        const __half2 f01 = *(const __half2*)(hrow + c4);
        const __half2 f23 = *(const __half2*)(hrow + c4 + 2);
        const __half2 g01 = *(const __half2*)(hrow + HN + c4);
        const __half2 g23 = *(const __half2*)(hrow + HN + c4 + 2);
        const float2 fa = __half22float2(f01), fb = __half22float2(f23);
        const float2 ga = __half22float2(g01), gb = __half22float2(g23);
        float4 m;
        m.x = sigmoida(fa.x * ssc[c4 + 0] + ssh[c4 + 0]) * tanha(ga.x * ssc[HN + c4 + 0] + ssh[HN + c4 + 0]);
        m.y = sigmoida(fa.y * ssc[c4 + 1] + ssh[c4 + 1]) * tanha(ga.y * ssc[HN + c4 + 1] + ssh[HN + c4 + 1]);
        m.z = sigmoida(fb.x * ssc[c4 + 2] + ssh[c4 + 2]) * tanha(gb.x * ssc[HN + c4 + 2] + ssh[HN + c4 + 2]);
        m.w = sigmoida(fb.y * ssc[c4 + 3] + ssh[c4 + 3]) * tanha(gb.y * ssc[HN + c4 + 3] + ssh[HN + c4 + 3]);
        const long long idx = is64 ? ((const long long*)ibuf)[e]
                                   : (long long)((const int*)ibuf)[e];
        float* dst = g_agg + idx * HN + c4;
        asm volatile("red.global.add.v4.f32 [%0], {%1, %2, %3, %4};"
                     :: "l"(dst), "f"(m.x), "f"(m.y), "f"(m.z), "f"(m.w) : "memory");
    }
}

// ---------------- BN2 + final ----------------
__global__ void stats2_kernel(int N) {
    const int t = blockIdx.x * blockDim.x + threadIdx.x;
    const int col = t & (HN - 1);
    const int r0 = t >> 7;
    const int rs = (gridDim.x * blockDim.x) >> 7;
    float s = 0.f, sq = 0.f;
    for (long long r = r0; r < N; r += rs) {
        const float v = g_agg[r * HN + col];
        s += v; sq = fmaf(v, v, sq);
    }
    atomicAdd(&g_stats2[col], s);
    atomicAdd(&g_stats2[HN + col], sq);
}

__global__ void final_kernel(const float* __restrict__ node_emb,
                             const float* __restrict__ gamma2,
                             const float* __restrict__ beta2,
                             float* __restrict__ out, int total, float invN) {
    const int t = blockIdx.x * blockDim.x + threadIdx.x;
    if (t >= total) return;
    const int col = t & (HN - 1);
    const float mu  = g_stats2[col] * invN;
    const float var = g_stats2[HN + col] * invN - mu * mu;
    const float c1  = (g_agg[t] - mu) * rsqrtf(var + EPS) * gamma2[col] + beta2[col];
    out[t] = tanhf_(node_emb[t] + c1);
}

// ---------------- launch ----------------
extern "C" void kernel_launch(void* const* d_in, const int* in_sizes, int n_in,
                              void* d_out, int out_size) {
    const float* node_emb = (const float*)d_in[0];
    const float* edge_emb = (const float*)d_in[1];
    const void*  ibuf     = d_in[2];
    const float* W1       = (const float*)d_in[3];
    const float* b1       = (const float*)d_in[4];
    const float* gamma1   = (const float*)d_in[5];
    const float* beta1    = (const float*)d_in[6];
    const float* gamma2   = (const float*)d_in[7];
    const float* beta2    = (const float*)d_in[8];
    float* out = (float*)d_out;

    const int N = in_sizes[0] / HN;
    const int E = in_sizes[1] / HN;

    static bool attr_done = false;
    if (!attr_done) {
        cudaFuncSetAttribute(mma_gemm<0>, cudaFuncAttributeMaxDynamicSharedMemorySize, SMEM_SZ);
        cudaFuncSetAttribute(mma_gemm<1>, cudaFuncAttributeMaxDynamicSharedMemorySize, SMEM_SZ);
        attr_done = true;
    }

    float*  g_P_ptr;  cudaGetSymbolAddress((void**)&g_P_ptr, g_P);
    __half* g_h_ptr;  cudaGetSymbolAddress((void**)&g_h_ptr, g_h16);
    uint4*  g_Ae_ptr; cudaGetSymbolAddress((void**)&g_Ae_ptr, g_Ae);
    uint4*  g_An_ptr; cudaGetSymbolAddress((void**)&g_An_ptr, g_An);

    detect_kernel<<<1, 32>>>((const unsigned*)ibuf);
    zero_kernel<<<4096, 256>>>(N * HN);
    prepW_kernel<<<64, 256>>>(W1);

    const int unitsN = NBLK_N * 1024;
    const int unitsE = NBLK_E * 1024;
    prepA_kernel<<<(unitsN + 255) / 256, 256>>>(node_emb, g_An_ptr, N, unitsN);
    prepA_kernel<<<(unitsE + 255) / 256, 256>>>(edge_emb, g_Ae_ptr, E, unitsE);

    mma_gemm<0><<<296, 256, SMEM_SZ>>>(g_An_ptr, b1, ibuf, g_P_ptr, N);
    mma_gemm<1><<<296, 256, SMEM_SZ>>>(g_Ae_ptr, b1, ibuf, g_h_ptr, E);

    finalize1_kernel<<<1, 256>>>(gamma1, beta1, 1.0f / (float)E);
    gate_scatter_kernel<<<8192, 256>>>(ibuf, E);

    stats2_kernel<<<1024, 256>>>(N);
    final_kernel<<<(N * HN + 255) / 256, 256>>>(node_emb, gamma2, beta2, out,
                                                N * HN, 1.0f / (float)N);
}

// round 13
// speedup vs baseline: 1.4383x; 1.1207x over previous
#include <cuda_runtime.h>
#include <cuda_fp16.h>
#include <cstdint>

#define HN 128
#define FF 256
#define NMAX 50048
#define EMAX 800000
#define EPS 1e-5f
#define NBLK_N (NMAX / 64)    // 782
#define NBLK_E (EMAX / 64)    // 12500
#define DEPTH 4

// ---------------- static scratch ----------------
__device__ float  g_P[(size_t)NMAX * FF];
__device__ float  g_agg[(size_t)NMAX * HN];
__device__ uint4  g_Ae[(size_t)NBLK_E * 1024];   // edge A, fp16 frag-packed
__device__ uint4  g_An[(size_t)NBLK_N * 1024];   // node A, fp16 frag-packed
__device__ uint2  g_Wt16[2][2][4096];            // [mode][half] B fp16 frag-packed (pass1/P)
__device__ uint2  g_Wt2[8192];                   // pass2 B, (filter,core)-interleaved pack
__device__ float  g_stats1[2 * FF];
__device__ float  g_stats2[2 * HN];
__device__ float  g_scale[FF];
__device__ float  g_shift[FF];
__device__ int    g_is64;

// ---------------- helpers ----------------
__device__ __forceinline__ uint32_t smem_u32(const void* p) {
    uint32_t a;
    asm("{ .reg .u64 t; cvta.to.shared.u64 t, %1; cvt.u32.u64 %0, t; }" : "=r"(a) : "l"(p));
    return a;
}
__device__ __forceinline__ float tanhf_(float x) {      // final output
    float t = __expf(2.f * x);
    return 1.f - __fdividef(2.f, t + 1.f);
}
__device__ __forceinline__ float tanha(float x) {
    float y; asm("tanh.approx.f32 %0, %1;" : "=f"(y) : "f"(x)); return y;
}
__device__ __forceinline__ float sigmoida(float x) {
    return fmaf(tanha(x * 0.5f), 0.5f, 0.5f);
}
__device__ __forceinline__ void mma16(float* c, const uint4 a, const uint2 b) {
    asm volatile("mma.sync.aligned.m16n8k16.row.col.f32.f16.f16.f32 "
                 "{%0,%1,%2,%3},{%4,%5,%6,%7},{%8,%9},{%0,%1,%2,%3};"
                 : "+f"(c[0]), "+f"(c[1]), "+f"(c[2]), "+f"(c[3])
                 : "r"(a.x), "r"(a.y), "r"(a.z), "r"(a.w), "r"(b.x), "r"(b.y));
}
__device__ __forceinline__ uint32_t h2u(__half2 h) {
    return *reinterpret_cast<uint32_t*>(&h);
}
__device__ __forceinline__ void cpasync16(uint32_t dst, const void* src) {
    asm volatile("cp.async.cg.shared.global [%0], [%1], 16;"
                 :: "r"(dst), "l"(src) : "memory");
}
#define CP_COMMIT() asm volatile("cp.async.commit_group;" ::: "memory")
__device__ __forceinline__ void cp_wait(int n) {
    if (n == 0)      asm volatile("cp.async.wait_group 0;" ::: "memory");
    else if (n == 1) asm volatile("cp.async.wait_group 1;" ::: "memory");
    else if (n == 2) asm volatile("cp.async.wait_group 2;" ::: "memory");
    else             asm volatile("cp.async.wait_group 3;" ::: "memory");
}
__device__ __forceinline__ void lds128(uint4& r, uint32_t addr) {
    asm volatile("ld.shared.v4.u32 {%0,%1,%2,%3}, [%4];"
                 : "=r"(r.x), "=r"(r.y), "=r"(r.z), "=r"(r.w) : "r"(addr));
}

// pass1 smem map
#define ABUF_OFF  32768
#define SSTAT_OFF 98304
#define SMEM_SZ   99328
// pass2 smem map: B2 64KB | ss 2KB | ring 8 warps x 4KB
#define B2_BYTES  65536
#define SS_OFF    65536
#define RING_OFF  67584
#define SMEM2_SZ  100352

// ---------------- small kernels ----------------
__global__ void detect_kernel(const unsigned* __restrict__ u) {
    unsigned v = 0;
    for (int k = threadIdx.x; k < 64; k += 32) v |= u[2 * k + 1];
#pragma unroll
    for (int o = 16; o; o >>= 1) v |= __shfl_xor_sync(0xffffffffu, v, o);
    if (threadIdx.x == 0) g_is64 = (v == 0) ? 1 : 0;
}

__global__ void zero_kernel(int aggCount) {
    const int stride = gridDim.x * blockDim.x;
    const int t0 = blockIdx.x * blockDim.x + threadIdx.x;
    for (int j = t0; j < aggCount; j += stride) g_agg[j] = 0.f;
    if (t0 < 2 * FF) g_stats1[t0] = 0.f;
    if (t0 < 2 * HN) g_stats2[t0] = 0.f;
}

// A pack: unit gid = ((block*8 + ks)*4 + mt)*32 + lane -> one uint4
__global__ void prepA_kernel(const float* __restrict__ A, uint4* __restrict__ dst,
                             int M, int nunits) {
    const int gid = blockIdx.x * blockDim.x + threadIdx.x;
    if (gid >= nunits) return;
    const int lane = gid & 31, mt = (gid >> 5) & 3, ks = (gid >> 7) & 7;
    const int block = gid >> 10;
    const int r0 = block * 64 + mt * 16 + (lane >> 2);
    const int r1 = r0 + 8;
    const int c0 = ks * 16 + (lane & 3) * 2;
    float2 v00 = make_float2(0.f, 0.f), v01 = v00, v10 = v00, v11 = v00;
    if (r0 < M) {
        v00 = *(const float2*)(A + (size_t)r0 * HN + c0);
        v01 = *(const float2*)(A + (size_t)r0 * HN + c0 + 8);
    }
    if (r1 < M) {
        v10 = *(const float2*)(A + (size_t)r1 * HN + c0);
        v11 = *(const float2*)(A + (size_t)r1 * HN + c0 + 8);
    }
    uint4 o;
    o.x = h2u(__floats2half2_rn(v00.x, v00.y));
    o.y = h2u(__floats2half2_rn(v10.x, v10.y));
    o.z = h2u(__floats2half2_rn(v01.x, v01.y));
    o.w = h2u(__floats2half2_rn(v11.x, v11.y));
    dst[gid] = o;
}

// B pack for pass1 / P GEMM (R8)
__global__ void prepW_kernel(const float* __restrict__ W1) {
    const int gid = blockIdx.x * blockDim.x + threadIdx.x;
    if (gid >= 16384) return;
    const int lane = gid & 31, nt = (gid >> 5) & 3, wn = (gid >> 7) & 3;
    const int ks = (gid >> 9) & 7, hf = (gid >> 12) & 1, mode = gid >> 13;
    const int n = hf * 128 + wn * 32 + nt * 8 + (lane >> 2);
    const int k = ks * 16 + (lane & 3) * 2 + mode * HN;
    uint2 o;
    o.x = h2u(__floats2half2_rn(W1[(size_t)k * FF + n], W1[(size_t)(k + 1) * FF + n]));
    o.y = h2u(__floats2half2_rn(W1[(size_t)(k + 8) * FF + n], W1[(size_t)(k + 9) * FF + n]));
    g_Wt16[mode][hf][gid & 4095] = o;
}

// B pack for pass2 (gate): 256 packed cols, pcol = 2*k_local + fc
// unit gid = (ks*32 + g)*32 + lane; g = wn*8 + nt
// pcol_local = lane>>2; j = pcol_local>>1; fc = pcol_local&1
// orig filter col = wn*32 + j*8 + nt ; orig n = filter + fc*128 ; k rows of W_bot
__global__ void prepW2_kernel(const float* __restrict__ W1) {
    const int gid = blockIdx.x * blockDim.x + threadIdx.x;
    if (gid >= 8192) return;
    const int lane = gid & 31, g = (gid >> 5) & 31, ks = gid >> 10;
    const int pl = lane >> 2, j = pl >> 1, fc = pl & 1;
    const int nt = g & 7, wn = g >> 3;
    const int n = wn * 32 + j * 8 + nt + fc * 128;
    const int k = HN + ks * 16 + (lane & 3) * 2;
    uint2 o;
    o.x = h2u(__floats2half2_rn(W1[(size_t)k * FF + n], W1[(size_t)(k + 1) * FF + n]));
    o.y = h2u(__floats2half2_rn(W1[(size_t)(k + 8) * FF + n], W1[(size_t)(k + 9) * FF + n]));
    g_Wt2[gid] = o;
}

// ---------------- pass1 GEMM (R12 structure) ----------------
// MODE 0: g_P (fp32) = node_emb @ W_top + b1
// MODE 1: BN1 column stats of (edge_emb @ W_bot + g_P[i[row]]) -- NO h store
template <int MODE>
__global__ __launch_bounds__(256, 2) void mma_gemm(
    const uint4* __restrict__ Apk, const float* __restrict__ b1,
    const void* __restrict__ ibuf, float* __restrict__ outv, int M)
{
    extern __shared__ char smem[];
    uint2* Bs = (uint2*)smem;
    float* sstat = (float*)(smem + SSTAT_OFF);

    const int tid = threadIdx.x, lane = tid & 31, wid = tid >> 5;
    const int wm = wid & 1, wn = wid >> 1;
    const int ntiles = (M + 127) >> 7;
    const long long njobs = (long long)ntiles * 2;
    const int G = gridDim.x;
    const int halfc = blockIdx.x & 1;
    const int is64 = (MODE == 1) ? g_is64 : 0;

    const uint32_t wbuf = smem_u32(smem) + ABUF_OFF + (uint32_t)wid * 8192
                          + (uint32_t)lane * 16;

    {   // B pack -> smem, once
        const uint4* src = (const uint4*)&g_Wt16[MODE][halfc][0];
        uint4* dstv = (uint4*)Bs;
        for (int i = tid; i < 2048; i += 256) dstv[i] = src[i];
    }
    if (MODE == 1) sstat[tid] = 0.f;
    __syncthreads();

    float acc[4][4][4];
#pragma unroll
    for (int mt = 0; mt < 4; mt++)
#pragma unroll
        for (int nt = 0; nt < 4; nt++)
#pragma unroll
            for (int r = 0; r < 4; r++) acc[mt][nt][r] = 0.f;

    for (long long job = blockIdx.x; job < njobs; job += G) {
        const long long tile = job >> 1;
        const uint4* abase = Apk + ((tile * 2 + wm) << 10) + lane;

#pragma unroll
        for (int p = 0; p < DEPTH; p++) {
#pragma unroll
            for (int mt = 0; mt < 4; mt++)
                cpasync16(wbuf + (uint32_t)((p * 4 + mt) << 9),
                          abase + p * 128 + mt * 32);
            CP_COMMIT();
        }

#pragma unroll
        for (int ks = 0; ks < 8; ks++) {
            const int wn_ = (7 - ks < DEPTH - 1) ? (7 - ks) : (DEPTH - 1);
            cp_wait(wn_);
            uint2 bfr[4];
#pragma unroll
            for (int nt = 0; nt < 4; nt++)
                bfr[nt] = Bs[(ks * 16 + wn * 4 + nt) * 32 + lane];
            uint4 a[4];
#pragma unroll
            for (int mt = 0; mt < 4; mt++)
                lds128(a[mt], wbuf + (uint32_t)((((ks % DEPTH) * 4) + mt) << 9));
            if (ks + DEPTH < 8) {
#pragma unroll
                for (int mt = 0; mt < 4; mt++)
                    cpasync16(wbuf + (uint32_t)(((((ks + DEPTH) % DEPTH) * 4) + mt) << 9),
                              abase + (ks + DEPTH) * 128 + mt * 32);
                CP_COMMIT();
            }
#pragma unroll
            for (int mt = 0; mt < 4; mt++)
#pragma unroll
                for (int nt = 0; nt < 4; nt++)
                    mma16(acc[mt][nt], a[mt], bfr[nt]);
        }

        // ---- epilogue ----
        const long long rbase = tile << 7;
        float s[4][2], q[4][2];
        if (MODE == 1) {
#pragma unroll
            for (int nt = 0; nt < 4; nt++) {
                s[nt][0] = s[nt][1] = 0.f; q[nt][0] = q[nt][1] = 0.f;
            }
        }
#pragma unroll
        for (int mt = 0; mt < 4; mt++) {
            long long pb[2]; bool valid[2]; long long rown[2];
#pragma unroll
            for (int h = 0; h < 2; h++) {
                const long long row = rbase + wm * 64 + mt * 16 + (lane >> 2) + h * 8;
                rown[h] = row;
                valid[h] = row < (long long)M;
                pb[h] = 0;
                if (MODE == 1 && valid[h]) {
                    const long long idx = is64 ? ((const long long*)ibuf)[row]
                                               : (long long)((const int*)ibuf)[row];
                    pb[h] = idx * FF;
                }
            }
#pragma unroll
            for (int nt = 0; nt < 4; nt++) {
                const int c0 = halfc * 128 + wn * 32 + nt * 8 + 2 * (lane & 3);
#pragma unroll
                for (int h = 0; h < 2; h++) {
                    if (!valid[h]) continue;
                    if (MODE == 0) {
                        const float2 add = *(const float2*)(b1 + c0);
                        float2 o;
                        o.x = acc[mt][nt][2 * h] + add.x;
                        o.y = acc[mt][nt][2 * h + 1] + add.y;
                        *(float2*)(outv + rown[h] * FF + c0) = o;
                    } else {
                        const float2 p = *(const float2*)(g_P + pb[h] + c0);
                        const float ox = acc[mt][nt][2 * h] + p.x;
                        const float oy = acc[mt][nt][2 * h + 1] + p.y;
                        s[nt][0] += ox; q[nt][0] = fmaf(ox, ox, q[nt][0]);
                        s[nt][1] += oy; q[nt][1] = fmaf(oy, oy, q[nt][1]);
                    }
                }
                acc[mt][nt][0] = 0.f; acc[mt][nt][1] = 0.f;
                acc[mt][nt][2] = 0.f; acc[mt][nt][3] = 0.f;
            }
        }
        if (MODE == 1) {
#pragma unroll
            for (int o = 4; o < 32; o <<= 1) {
#pragma unroll
                for (int nt = 0; nt < 4; nt++) {
                    s[nt][0] += __shfl_xor_sync(0xffffffffu, s[nt][0], o);
                    s[nt][1] += __shfl_xor_sync(0xffffffffu, s[nt][1], o);
                    q[nt][0] += __shfl_xor_sync(0xffffffffu, q[nt][0], o);
                    q[nt][1] += __shfl_xor_sync(0xffffffffu, q[nt][1], o);
                }
            }
            if (lane < 4) {
#pragma unroll
                for (int nt = 0; nt < 4; nt++) {
                    const int lc = wn * 32 + nt * 8 + 2 * lane;
                    atomicAdd(&sstat[lc], s[nt][0]);
                    atomicAdd(&sstat[lc + 1], s[nt][1]);
                    atomicAdd(&sstat[128 + lc], q[nt][0]);
                    atomicAdd(&sstat[128 + lc + 1], q[nt][1]);
                }
            }
        }
    }
    if (MODE == 1) {
        __syncthreads();
        if (tid < 128) {
            atomicAdd(&g_stats1[halfc * 128 + tid], sstat[tid]);
            atomicAdd(&g_stats1[256 + halfc * 128 + tid], sstat[128 + tid]);
        }
    }
}

// ---------------- BN1 finalize ----------------
__global__ void finalize1_kernel(const float* __restrict__ gamma1,
                                 const float* __restrict__ beta1, float invE) {
    const int j = threadIdx.x;
    const float mu  = g_stats1[j] * invE;
    const float var = g_stats1[FF + j] * invE - mu * mu;
    const float s   = gamma1[j] * rsqrtf(var + EPS);
    g_scale[j] = s;
    g_shift[j] = beta1[j] - mu * s;
}

// ---------------- pass2: GEMM + gate + scatter, fused ----------------
// Job = one 64-row A block. CTA computes 64 x 256 (full interleaved cols).
// 8 warps: wm = wid&1 (32 rows), wn = wid>>1 (64 packed cols).
// acc[mt][nt][2h+fc]: fc=0 filter, fc=1 core; k = wn*32 + (lane&3)*8 + nt.
__global__ __launch_bounds__(256, 2) void gemm_gate(
    const uint4* __restrict__ Apk, const void* __restrict__ ibuf, int E)
{
    extern __shared__ char smem[];
    uint2* B2s = (uint2*)smem;
    float* ss = (float*)(smem + SS_OFF);      // [0:256) scale, [256:512) shift

    const int tid = threadIdx.x, lane = tid & 31, wid = tid >> 5;
    const int wm = wid & 1, wn = wid >> 1;
    const int nblk = (E + 63) >> 6;
    const int G = gridDim.x;
    const int is64 = g_is64;

    {
        const uint4* src = (const uint4*)&g_Wt2[0];
        uint4* dstv = (uint4*)B2s;
        for (int i = tid; i < 4096; i += 256) dstv[i] = src[i];
    }
    ss[tid] = g_scale[tid];
    ss[256 + tid] = g_shift[tid];
    __syncthreads();

    const uint32_t wbuf = smem_u32(smem) + RING_OFF + (uint32_t)wid * 4096
                          + (uint32_t)lane * 16;
    const int kbase = wn * 32 + (lane & 3) * 8;

    float acc[2][8][4];
#pragma unroll
    for (int mt = 0; mt < 2; mt++)
#pragma unroll
        for (int nt = 0; nt < 8; nt++)
#pragma unroll
            for (int r = 0; r < 4; r++) acc[mt][nt][r] = 0.f;

    for (int job = blockIdx.x; job < nblk; job += G) {
        const uint4* abase = Apk + ((long long)job << 10) + lane;

        // prologue: fill ring (per-warp slots: 2 frags x DEPTH)
#pragma unroll
        for (int p = 0; p < DEPTH; p++) {
#pragma unroll
            for (int mt = 0; mt < 2; mt++)
                cpasync16(wbuf + (uint32_t)((p * 2 + mt) << 9),
                          abase + (p * 4 + wm * 2 + mt) * 32);
            CP_COMMIT();
        }

#pragma unroll
        for (int ks = 0; ks < 8; ks++) {
            const int wn_ = (7 - ks < DEPTH - 1) ? (7 - ks) : (DEPTH - 1);
            cp_wait(wn_);
            uint2 bfr[8];
#pragma unroll
            for (int nt = 0; nt < 8; nt++)
                bfr[nt] = B2s[(ks * 32 + wn * 8 + nt) * 32 + lane];
            uint4 a[2];
#pragma unroll
            for (int mt = 0; mt < 2; mt++)
                lds128(a[mt], wbuf + (uint32_t)((((ks % DEPTH) * 2) + mt) << 9));
            if (ks + DEPTH < 8) {
#pragma unroll
                for (int mt = 0; mt < 2; mt++)
                    cpasync16(wbuf + (uint32_t)(((((ks + DEPTH) % DEPTH) * 2) + mt) << 9),
                              abase + ((ks + DEPTH) * 4 + wm * 2 + mt) * 32);
                CP_COMMIT();
            }
#pragma unroll
            for (int mt = 0; mt < 2; mt++)
#pragma unroll
                for (int nt = 0; nt < 8; nt++)
                    mma16(acc[mt][nt], a[mt], bfr[nt]);
        }

        // ---- fused gate + scatter epilogue ----
#pragma unroll
        for (int mt = 0; mt < 2; mt++) {
#pragma unroll
            for (int h = 0; h < 2; h++) {
                const long long row = (long long)job * 64 + wm * 32 + mt * 16
                                      + (lane >> 2) + h * 8;
                if (row < (long long)E) {
                    const long long idx = is64 ? ((const long long*)ibuf)[row]
                                               : (long long)((const int*)ibuf)[row];
                    const float* prow = g_P + idx * FF;
                    const float4 pf0 = *(const float4*)(prow + kbase);
                    const float4 pf1 = *(const float4*)(prow + kbase + 4);
                    const float4 pc0 = *(const float4*)(prow + 128 + kbase);
                    const float4 pc1 = *(const float4*)(prow + 128 + kbase + 4);
                    const float pf[8] = {pf0.x, pf0.y, pf0.z, pf0.w,
                                         pf1.x, pf1.y, pf1.z, pf1.w};
                    const float pc[8] = {pc0.x, pc0.y, pc0.z, pc0.w,
                                         pc1.x, pc1.y, pc1.z, pc1.w};
                    float m[8];
#pragma unroll
                    for (int nt = 0; nt < 8; nt++) {
                        const int k = kbase + nt;
                        const float hF = acc[mt][nt][2 * h] + pf[nt];
                        const float hC = acc[mt][nt][2 * h + 1] + pc[nt];
                        m[nt] = sigmoida(hF * ss[k] + ss[256 + k])
                              * tanha(hC * ss[128 + k] + ss[384 + k]);
                    }
                    float* dst = g_agg + idx * HN + kbase;
                    asm volatile("red.global.add.v4.f32 [%0], {%1, %2, %3, %4};"
                                 :: "l"(dst), "f"(m[0]), "f"(m[1]), "f"(m[2]), "f"(m[3]) : "memory");
                    asm volatile("red.global.add.v4.f32 [%0], {%1, %2, %3, %4};"
                                 :: "l"(dst + 4), "f"(m[4]), "f"(m[5]), "f"(m[6]), "f"(m[7]) : "memory");
                }
            }
#pragma unroll
            for (int nt = 0; nt < 8; nt++) {
                acc[mt][nt][0] = 0.f; acc[mt][nt][1] = 0.f;
                acc[mt][nt][2] = 0.f; acc[mt][nt][3] = 0.f;
            }
        }
    }
}

// ---------------- BN2 + final ----------------
__global__ void stats2_kernel(int N) {
    const int t = blockIdx.x * blockDim.x + threadIdx.x;
    const int col = t & (HN - 1);
    const int r0 = t >> 7;
    const int rs = (gridDim.x * blockDim.x) >> 7;
    float s = 0.f, sq = 0.f;
    for (long long r = r0; r < N; r += rs) {
        const float v = g_agg[r * HN + col];
        s += v; sq = fmaf(v, v, sq);
    }
    atomicAdd(&g_stats2[col], s);
    atomicAdd(&g_stats2[HN + col], sq);
}

__global__ void final_kernel(const float* __restrict__ node_emb,
                             const float* __restrict__ gamma2,
                             const float* __restrict__ beta2,
                             float* __restrict__ out, int total, float invN) {
    const int t = blockIdx.x * blockDim.x + threadIdx.x;
    if (t >= total) return;
    const int col = t & (HN - 1);
    const float mu  = g_stats2[col] * invN;
    const float var = g_stats2[HN + col] * invN - mu * mu;
    const float c1  = (g_agg[t] - mu) * rsqrtf(var + EPS) * gamma2[col] + beta2[col];
    out[t] = tanhf_(node_emb[t] + c1);
}

// ---------------- launch ----------------
extern "C" void kernel_launch(void* const* d_in, const int* in_sizes, int n_in,
                              void* d_out, int out_size) {
    const float* node_emb = (const float*)d_in[0];
    const float* edge_emb = (const float*)d_in[1];
    const void*  ibuf     = d_in[2];
    const float* W1       = (const float*)d_in[3];
    const float* b1       = (const float*)d_in[4];
    const float* gamma1   = (const float*)d_in[5];
    const float* beta1    = (const float*)d_in[6];
    const float* gamma2   = (const float*)d_in[7];
    const float* beta2    = (const float*)d_in[8];
    float* out = (float*)d_out;

    const int N = in_sizes[0] / HN;
    const int E = in_sizes[1] / HN;

    static bool attr_done = false;
    if (!attr_done) {
        cudaFuncSetAttribute(mma_gemm<0>, cudaFuncAttributeMaxDynamicSharedMemorySize, SMEM_SZ);
        cudaFuncSetAttribute(mma_gemm<1>, cudaFuncAttributeMaxDynamicSharedMemorySize, SMEM_SZ);
        cudaFuncSetAttribute(gemm_gate, cudaFuncAttributeMaxDynamicSharedMemorySize, SMEM2_SZ);
        attr_done = true;
    }

    float*  g_P_ptr;  cudaGetSymbolAddress((void**)&g_P_ptr, g_P);
    uint4*  g_Ae_ptr; cudaGetSymbolAddress((void**)&g_Ae_ptr, g_Ae);
    uint4*  g_An_ptr; cudaGetSymbolAddress((void**)&g_An_ptr, g_An);

    detect_kernel<<<1, 32>>>((const unsigned*)ibuf);
    zero_kernel<<<4096, 256>>>(N * HN);
    prepW_kernel<<<64, 256>>>(W1);
    prepW2_kernel<<<32, 256>>>(W1);

    const int unitsN = NBLK_N * 1024;
    const int unitsE = NBLK_E * 1024;
    prepA_kernel<<<(unitsN + 255) / 256, 256>>>(node_emb, g_An_ptr, N, unitsN);
    prepA_kernel<<<(unitsE + 255) / 256, 256>>>(edge_emb, g_Ae_ptr, E, unitsE);

    mma_gemm<0><<<296, 256, SMEM_SZ>>>(g_An_ptr, b1, ibuf, g_P_ptr, N);
    mma_gemm<1><<<296, 256, SMEM_SZ>>>(g_Ae_ptr, b1, ibuf, nullptr, E);

    finalize1_kernel<<<1, 256>>>(gamma1, beta1, 1.0f / (float)E);

    gemm_gate<<<296, 256, SMEM2_SZ>>>(g_Ae_ptr, ibuf, E);

    stats2_kernel<<<1024, 256>>>(N);
    final_kernel<<<(N * HN + 255) / 256, 256>>>(node_emb, gamma2, beta2, out,
                                                N * HN, 1.0f / (float)N);
}